// round 15
// baseline (speedup 1.0000x reference)
#include <cuda_runtime.h>
#include <cuda_fp16.h>
#include <cuda_bf16.h>
#include <math.h>
#include <stdint.h>

#define S 2048
#define H 1536
#define NQ 12
#define NKV 2
#define D 128
#define IFF 8960
#define LAYERS 4
#define QDIM (NQ*D)      // 1536
#define KVDIM (NKV*D)    // 256
#define QKVN 2048
#define GUN (2*IFF)      // 17920
#define EPS 1e-6f
#define SCALE 0.08838834764831845f

// ---------------- device scratch (allocation-free) ----------------
__device__ float g_x[S*H];
__device__ float g_qkv[S*QKVN];
__device__ __half g_a16[(size_t)S*H];
__device__ __half g_b16[(size_t)S*IFF];
__device__ __half g_q16h[(size_t)NQ*S*D];
__device__ __half g_q16l[(size_t)NQ*S*D];
__device__ __half g_k16[(size_t)NKV*S*D];
__device__ __half g_v16[(size_t)NKV*S*D];

__device__ __forceinline__ uint32_t pack_h2(__half a, __half b) {
    __half2 t; t.x = a; t.y = b;
    return *reinterpret_cast<uint32_t*>(&t);
}
__device__ __forceinline__ uint32_t smem_u32(const void* p) {
    uint32_t a;
    asm("{ .reg .u64 t; cvta.to.shared.u64 t, %1; cvt.u32.u64 %0, t; }" : "=r"(a) : "l"(p));
    return a;
}
__device__ __forceinline__ void mma_fp16(float* d, const uint32_t* a, uint32_t b0, uint32_t b1) {
    asm volatile(
        "mma.sync.aligned.m16n8k16.row.col.f32.f16.f16.f32 "
        "{%0,%1,%2,%3}, {%4,%5,%6,%7}, {%8,%9}, {%0,%1,%2,%3};"
        : "+f"(d[0]), "+f"(d[1]), "+f"(d[2]), "+f"(d[3])
        : "r"(a[0]), "r"(a[1]), "r"(a[2]), "r"(a[3]), "r"(b0), "r"(b1));
}
__device__ __forceinline__ void ldsm_x4(uint32_t* r, uint32_t addr) {
    asm volatile("ldmatrix.sync.aligned.m8n8.x4.shared.b16 {%0,%1,%2,%3}, [%4];"
        : "=r"(r[0]), "=r"(r[1]), "=r"(r[2]), "=r"(r[3]) : "r"(addr));
}
__device__ __forceinline__ void ldsm_x4t(uint32_t* r, uint32_t addr) {
    asm volatile("ldmatrix.sync.aligned.m8n8.x4.trans.shared.b16 {%0,%1,%2,%3}, [%4];"
        : "=r"(r[0]), "=r"(r[1]), "=r"(r[2]), "=r"(r[3]) : "r"(addr));
}
#define CP_A16(dst, src) asm volatile("cp.async.ca.shared.global [%0], [%1], 16;" :: "r"(dst), "l"(src) : "memory")
#define CP_COMMIT()      asm volatile("cp.async.commit_group;" ::: "memory")
#define CP_WAIT(n)       asm volatile("cp.async.wait_group %0;" :: "n"(n) : "memory")

// ---------------- copy ----------------
__global__ void copy_kernel(const float4* __restrict__ src, float4* __restrict__ dst, int n) {
    int i = blockIdx.x * blockDim.x + threadIdx.x;
    if (i < n) dst[i] = src[i];
}

// ---------------- RMSNorm (fp32 out, final only) ----------------
__global__ void rmsnorm_kernel(const float* __restrict__ x, const float* __restrict__ w,
                               float* __restrict__ out) {
    int row = blockIdx.x;
    const float* xr = x + (size_t)row * H;
    float ss = 0.f;
    for (int c = threadIdx.x; c < H; c += 256) { float v = xr[c]; ss += v * v; }
    __shared__ float red[256];
    red[threadIdx.x] = ss;
    __syncthreads();
    for (int off = 128; off > 0; off >>= 1) {
        if (threadIdx.x < off) red[threadIdx.x] += red[threadIdx.x + off];
        __syncthreads();
    }
    float rs = 1.0f / sqrtf(red[0] / (float)H + EPS);
    float* orow = out + (size_t)row * H;
    for (int c = threadIdx.x; c < H; c += 256) orow[c] = xr[c] * rs * w[c];
}

// ---------------- RMSNorm -> fp16 ----------------
__global__ void rmsnorm16_kernel(const float* __restrict__ x, const float* __restrict__ w,
                                 __half* __restrict__ out) {
    int row = blockIdx.x;
    const float* xr = x + (size_t)row * H;
    float ss = 0.f;
    for (int c = threadIdx.x; c < H; c += 256) { float v = xr[c]; ss += v * v; }
    __shared__ float red[256];
    red[threadIdx.x] = ss;
    __syncthreads();
    for (int off = 128; off > 0; off >>= 1) {
        if (threadIdx.x < off) red[threadIdx.x] += red[threadIdx.x + off];
        __syncthreads();
    }
    float rs = 1.0f / sqrtf(red[0] / (float)H + EPS);
    for (int c = threadIdx.x * 2; c < H; c += 512) {
        float v0 = xr[c] * rs * w[c];
        float v1 = xr[c + 1] * rs * w[c + 1];
        *(uint32_t*)(out + (size_t)row * H + c) =
            pack_h2(__float2half_rn(v0), __float2half_rn(v1));
    }
}

// ---------------- warp-MMA fp16 GEMM with fused fp32->fp16 B conversion ----------------
// EPI 0: QKV (3 W sources, 2-pass hi/lo, +bias -> fp32)
// EPI 1: plain W (NPASS passes, += R -> fp32)
// EPI 2: gate/up interleave (1-pass, silu(g)*u -> fp16)
#define APITCH 40
#define PB 136
#define B_BYTES (32 * PB * 2)            // 8704
#define A_BYTES (128 * APITCH * 2)       // 10240

template <int EPI, int NPASS>
__global__ void __launch_bounds__(256, 2) wgemm_kernel(
    const __half* __restrict__ A,
    const float* __restrict__ W0, const float* __restrict__ W1, const float* __restrict__ W2,
    const float* __restrict__ bq, const float* __restrict__ bk, const float* __restrict__ bv,
    const float* __restrict__ Rres, float* __restrict__ C, __half* __restrict__ C16,
    int K, int N, int Nout)
{
    constexpr int STAGE_BYTES = A_BYTES + NPASS * B_BYTES;
    extern __shared__ char smc[];
    uint32_t smb = smem_u32(smc);
    int tid = threadIdx.x, wid = tid >> 5, lane = tid & 31;
    int bm = blockIdx.x * 128, bn = blockIdx.y * 128;
    int mw = (wid & 3) * 32, nw = (wid >> 2) * 64;
    const int KS = K / 32;

    // A loader (cp.async, fp16)
    int arow = tid >> 1, akoff = (tid & 1) * 16;
    const __half* Ap = A + (size_t)(bm + arow) * K + akoff;
    uint32_t a_s = (uint32_t)(arow * APITCH + akoff) * 2;

    // B loader (LDG fp32 + convert + STS): thread covers 16 contiguous output cols
    int brow = tid >> 3, bcoff = (tid & 7) * 16;
    const float* bsrc;
    int ldsrc;
    if (EPI == 0) {
        int col = bn + bcoff;
        if (col < QDIM)              { bsrc = W0 + col;                ldsrc = QDIM; }
        else if (col < QDIM + KVDIM) { bsrc = W1 + (col - QDIM);       ldsrc = KVDIM; }
        else                         { bsrc = W2 + (col - QDIM - KVDIM); ldsrc = KVDIM; }
    } else if (EPI == 2) {
        int ci = bn + bcoff;
        int G = ci >> 5;
        int nsrc = ((G >> 1) << 5) + (ci & 31);
        bsrc = ((G & 1) ? W1 : W0) + nsrc;
        ldsrc = IFF;
    } else {
        bsrc = W0 + bn + bcoff;
        ldsrc = N;
    }
    uint32_t b_s = (uint32_t)(brow * PB + bcoff) * 2;

    float4 br[4];
    auto cpA = [&](int st, int k0) {
        uint32_t base = smb + (uint32_t)st * STAGE_BYTES;
        CP_A16(base + a_s,      Ap + k0);
        CP_A16(base + a_s + 16, Ap + k0 + 8);
    };
    auto ldgB = [&](int k0) {
        const float* p = bsrc + (size_t)(brow + k0) * ldsrc;
#pragma unroll
        for (int j = 0; j < 4; j++) br[j] = *(const float4*)(p + j * 4);
    };
    auto stsB = [&](int st) {
        char* p = smc + (size_t)st * STAGE_BYTES + A_BYTES + (brow * PB + bcoff) * 2;
        uint32_t hw[8], lw[8];
#pragma unroll
        for (int j = 0; j < 4; j++) {
            float v0 = (&br[j].x)[0], v1 = (&br[j].x)[1];
            float v2 = (&br[j].x)[2], v3 = (&br[j].x)[3];
            __half h0 = __float2half_rn(v0), h1 = __float2half_rn(v1);
            __half h2 = __float2half_rn(v2), h3 = __float2half_rn(v3);
            hw[j * 2]     = pack_h2(h0, h1);
            hw[j * 2 + 1] = pack_h2(h2, h3);
            if (NPASS == 2) {
                lw[j * 2]     = pack_h2(__float2half_rn(v0 - __half2float(h0)),
                                        __float2half_rn(v1 - __half2float(h1)));
                lw[j * 2 + 1] = pack_h2(__float2half_rn(v2 - __half2float(h2)),
                                        __float2half_rn(v3 - __half2float(h3)));
            }
        }
        *(uint4*)p        = make_uint4(hw[0], hw[1], hw[2], hw[3]);
        *(uint4*)(p + 16) = make_uint4(hw[4], hw[5], hw[6], hw[7]);
        if (NPASS == 2) {
            *(uint4*)(p + B_BYTES)      = make_uint4(lw[0], lw[1], lw[2], lw[3]);
            *(uint4*)(p + B_BYTES + 16) = make_uint4(lw[4], lw[5], lw[6], lw[7]);
        }
    };

    float acc[2][8][4];
#pragma unroll
    for (int mt = 0; mt < 2; mt++)
#pragma unroll
        for (int nt = 0; nt < 8; nt++)
#pragma unroll
            for (int e = 0; e < 4; e++) acc[mt][nt][e] = 0.f;

    const int frow = lane & 15, fk8 = (lane >> 4) << 3;
    const int loc = lane & 7, li = lane >> 3;

    cpA(0, 0); CP_COMMIT();
    ldgB(0); stsB(0);
    cpA(1, 32); CP_COMMIT();
    ldgB(32); stsB(1);

    int st = 0;
    for (int ks = 0; ks < KS; ks++) {
        CP_WAIT(1);
        __syncthreads();
        int st2 = st + 2; if (st2 >= 3) st2 -= 3;
        bool pre = (ks + 2 < KS);
        if (pre) {
            cpA(st2, (ks + 2) * 32);
            CP_COMMIT();
            ldgB((ks + 2) * 32);
        }
        uint32_t A32  = smb + (uint32_t)st * STAGE_BYTES;
        uint32_t Bh32 = A32 + A_BYTES;
        uint32_t Bl32 = Bh32 + B_BYTES;

#pragma unroll
        for (int kk = 0; kk < 32; kk += 16) {
            uint32_t ah[2][4];
#pragma unroll
            for (int mt = 0; mt < 2; mt++) {
                uint32_t off = (uint32_t)((mw + mt * 16 + frow) * APITCH + kk + fk8) * 2;
                ldsm_x4(ah[mt], A32 + off);
            }
#pragma unroll
            for (int p = 0; p < 4; p++) {
                uint32_t boff = (uint32_t)((kk + (li & 1) * 8 + loc) * PB
                                           + nw + p * 16 + (li >> 1) * 8) * 2;
                uint32_t bh[4];
                ldsm_x4t(bh, Bh32 + boff);
                uint32_t bl[4];
                if (NPASS == 2) ldsm_x4t(bl, Bl32 + boff);
#pragma unroll
                for (int o = 0; o < 2; o++) {
                    int nt = p * 2 + o;
                    uint32_t b0h = bh[o * 2], b1h = bh[o * 2 + 1];
#pragma unroll
                    for (int mt = 0; mt < 2; mt++) {
                        mma_fp16(acc[mt][nt], ah[mt], b0h, b1h);
                        if (NPASS == 2)
                            mma_fp16(acc[mt][nt], ah[mt], bl[o * 2], bl[o * 2 + 1]);
                    }
                }
            }
        }
        if (pre) stsB(st2);
        st++; if (st >= 3) st = 0;
    }

    // ---- epilogue ----
    if (EPI == 2) {
        int j = (bn + nw) >> 6;
#pragma unroll
        for (int mt = 0; mt < 2; mt++) {
#pragma unroll
            for (int nt = 0; nt < 4; nt++) {
                int r0 = bm + mw + mt * 16 + (lane >> 2);
                int col = (j << 5) + nt * 8 + (lane & 3) * 2;
                float av[4];
#pragma unroll
                for (int e = 0; e < 4; e++) {
                    float g = acc[mt][nt][e];
                    float u = acc[mt][nt + 4][e];
                    av[e] = g / (1.f + __expf(-g)) * u;
                }
                *(uint32_t*)(C16 + (size_t)r0 * Nout + col) =
                    pack_h2(__float2half_rn(av[0]), __float2half_rn(av[1]));
                *(uint32_t*)(C16 + (size_t)(r0 + 8) * Nout + col) =
                    pack_h2(__float2half_rn(av[2]), __float2half_rn(av[3]));
            }
        }
    } else {
#pragma unroll
        for (int mt = 0; mt < 2; mt++) {
#pragma unroll
            for (int nt = 0; nt < 8; nt++) {
                int r0 = bm + mw + mt * 16 + (lane >> 2);
                int col = bn + nw + nt * 8 + (lane & 3) * 2;
                float2 v0 = {acc[mt][nt][0], acc[mt][nt][1]};
                float2 v1 = {acc[mt][nt][2], acc[mt][nt][3]};
                if (EPI == 0) {
                    float b0, b1;
                    if (col < QDIM)              { b0 = bq[col];                b1 = bq[col + 1]; }
                    else if (col < QDIM + KVDIM) { b0 = bk[col - QDIM];         b1 = bk[col - QDIM + 1]; }
                    else                         { b0 = bv[col - QDIM - KVDIM]; b1 = bv[col - QDIM - KVDIM + 1]; }
                    v0.x += b0; v0.y += b1; v1.x += b0; v1.y += b1;
                } else {
                    float2 r0v = *(const float2*)(Rres + (size_t)r0 * N + col);
                    float2 r1v = *(const float2*)(Rres + (size_t)(r0 + 8) * N + col);
                    v0.x += r0v.x; v0.y += r0v.y;
                    v1.x += r1v.x; v1.y += r1v.y;
                }
                *(float2*)(C + (size_t)r0 * N + col) = v0;
                *(float2*)(C + (size_t)(r0 + 8) * N + col) = v1;
            }
        }
    }
}

// ---------------- RoPE -> fp16 Q split + fp16 K/V ----------------
__global__ void rope16_kernel(const float* __restrict__ qkv,
                              const float* __restrict__ cp, const float* __restrict__ sp,
                              __half* __restrict__ qh, __half* __restrict__ ql,
                              __half* __restrict__ k16, __half* __restrict__ v16) {
    int s = blockIdx.x, slot = blockIdx.y, d = threadIdx.x;
    float c = cp[s * D + d], sn = sp[s * D + d];
    const float* row;
    if (slot < NQ)            row = qkv + (size_t)s * QKVN + slot * D;
    else if (slot < NQ + NKV) row = qkv + (size_t)s * QKVN + QDIM + (slot - NQ) * D;
    else                      row = qkv + (size_t)s * QKVN + QDIM + KVDIM + (slot - NQ - NKV) * D;
    float a = row[d];
    float b = row[d ^ 64];
    float rot = (d < 64) ? -b : b;
    if (slot < NQ) {
        float val = a * c + rot * sn;
        __half hv = __float2half_rn(val);
        __half lv = __float2half_rn(val - __half2float(hv));
        size_t o = ((size_t)slot * S + s) * D + d;
        qh[o] = hv; ql[o] = lv;
    } else if (slot < NQ + NKV) {
        float val = a * c + rot * sn;
        k16[((size_t)(slot - NQ) * S + s) * D + d] = __float2half_rn(val);
    } else {
        v16[((size_t)(slot - NQ - NKV) * S + s) * D + d] = __float2half_rn(a);
    }
}

// ---------------- tensor-core causal flash attention ----------------
#define PKV 136
#define ATT_SMEM (128 * PKV * 2)

__global__ void __launch_bounds__(256, 1) attn_kernel(
    const __half* __restrict__ qh, const __half* __restrict__ ql,
    const __half* __restrict__ k16, const __half* __restrict__ v16,
    __half* __restrict__ o16)
{
    extern __shared__ __half sma[];
    uint32_t smb = smem_u32(sma);
    int tid = threadIdx.x, wid = tid >> 5, lane = tid & 31;
    int bq = (int)gridDim.x - 1 - (int)blockIdx.x;
    int h = blockIdx.y;
    int kvh = h / (NQ / NKV);
    int q0 = bq * 128;
    int wq0 = wid * 16;

    const int frow = lane & 15, fk8 = (lane >> 4) << 3;

    uint32_t qfh[8][4], qfl[8][4];
    {
        int row = tid >> 1, coff = (tid & 1) * 64;
        __half* dst = sma + row * PKV + coff;
        const __half* src = qh + ((size_t)h * S + q0 + row) * D + coff;
#pragma unroll
        for (int j = 0; j < 8; j++) *(uint4*)(dst + j * 8) = *(const uint4*)(src + j * 8);
        __syncthreads();
#pragma unroll
        for (int kd = 0; kd < 8; kd++)
            ldsm_x4(qfh[kd], smb + (uint32_t)((wq0 + frow) * PKV + kd * 16 + fk8) * 2);
        __syncthreads();
        const __half* src2 = ql + ((size_t)h * S + q0 + row) * D + coff;
#pragma unroll
        for (int j = 0; j < 8; j++) *(uint4*)(dst + j * 8) = *(const uint4*)(src2 + j * 8);
        __syncthreads();
#pragma unroll
        for (int kd = 0; kd < 8; kd++)
            ldsm_x4(qfl[kd], smb + (uint32_t)((wq0 + frow) * PKV + kd * 16 + fk8) * 2);
        __syncthreads();
    }

    auto cp_kv = [&](int st, int kt) {
        int row = tid >> 3, c16 = (tid & 7) * 16;
        const __half* ksrc = k16 + ((size_t)kvh * S + kt * 32 + row) * D + c16;
        const __half* vsrc = v16 + ((size_t)kvh * S + kt * 32 + row) * D + c16;
        uint32_t kdst = smb + (uint32_t)((st * 32 + row) * PKV + c16) * 2;
        uint32_t vdst = smb + (uint32_t)((64 + st * 32 + row) * PKV + c16) * 2;
        CP_A16(kdst, ksrc); CP_A16(kdst + 16, ksrc + 8);
        CP_A16(vdst, vsrc); CP_A16(vdst + 16, vsrc + 8);
    };

    float oacc[16][4];
#pragma unroll
    for (int nt = 0; nt < 16; nt++)
#pragma unroll
        for (int e = 0; e < 4; e++) oacc[nt][e] = 0.f;
    float mrow0 = -1e30f, mrow1 = -1e30f, lrow0 = 0.f, lrow1 = 0.f;

    const int nk = 4 * bq + 4;
    cp_kv(0, 0);
    CP_COMMIT();

    for (int kt = 0; kt < nk; kt++) {
        int st = kt & 1;
        if (kt + 1 < nk) {
            cp_kv(st ^ 1, kt + 1);
            CP_COMMIT();
            CP_WAIT(1);
        } else {
            CP_WAIT(0);
        }
        __syncthreads();

        float sc[4][4];
#pragma unroll
        for (int nt = 0; nt < 4; nt++)
#pragma unroll
            for (int e = 0; e < 4; e++) sc[nt][e] = 0.f;
        uint32_t kbase = smb + (uint32_t)(st * 32 * PKV) * 2;
#pragma unroll
        for (int kd = 0; kd < 8; kd++) {
            uint32_t bf0[4], bf1[4];
            ldsm_x4(bf0, kbase + (uint32_t)(frow * PKV + kd * 16 + fk8) * 2);
            ldsm_x4(bf1, kbase + (uint32_t)((16 + frow) * PKV + kd * 16 + fk8) * 2);
            mma_fp16(sc[0], qfh[kd], bf0[0], bf0[2]);
            mma_fp16(sc[1], qfh[kd], bf0[1], bf0[3]);
            mma_fp16(sc[2], qfh[kd], bf1[0], bf1[2]);
            mma_fp16(sc[3], qfh[kd], bf1[1], bf1[3]);
            mma_fp16(sc[0], qfl[kd], bf0[0], bf0[2]);
            mma_fp16(sc[1], qfl[kd], bf0[1], bf0[3]);
            mma_fp16(sc[2], qfl[kd], bf1[0], bf1[2]);
            mma_fp16(sc[3], qfl[kd], bf1[1], bf1[3]);
        }
        int r_lo = q0 + wq0 + (lane >> 2);
        if (kt >= 4 * bq) {
            int kk0 = kt * 32;
#pragma unroll
            for (int nt = 0; nt < 4; nt++) {
                int kc = kk0 + nt * 8 + (lane & 3) * 2;
#pragma unroll
                for (int e = 0; e < 4; e++) {
                    int key = kc + (e & 1);
                    int row = r_lo + ((e >> 1) << 3);
                    sc[nt][e] = (key > row) ? -1e30f : sc[nt][e] * SCALE;
                }
            }
        } else {
#pragma unroll
            for (int nt = 0; nt < 4; nt++)
#pragma unroll
                for (int e = 0; e < 4; e++) sc[nt][e] *= SCALE;
        }
        float mx0 = -1e30f, mx1 = -1e30f;
#pragma unroll
        for (int nt = 0; nt < 4; nt++) {
            mx0 = fmaxf(mx0, fmaxf(sc[nt][0], sc[nt][1]));
            mx1 = fmaxf(mx1, fmaxf(sc[nt][2], sc[nt][3]));
        }
        mx0 = fmaxf(mx0, __shfl_xor_sync(0xffffffffu, mx0, 1));
        mx0 = fmaxf(mx0, __shfl_xor_sync(0xffffffffu, mx0, 2));
        mx1 = fmaxf(mx1, __shfl_xor_sync(0xffffffffu, mx1, 1));
        mx1 = fmaxf(mx1, __shfl_xor_sync(0xffffffffu, mx1, 2));
        float mn0 = fmaxf(mrow0, mx0), mn1 = fmaxf(mrow1, mx1);
        float c0 = __expf(mrow0 - mn0), c1 = __expf(mrow1 - mn1);
        mrow0 = mn0; mrow1 = mn1;
        uint32_t pah[2][4], pal[2][4];
        float ps0 = 0.f, ps1 = 0.f;
#pragma unroll
        for (int b = 0; b < 2; b++) {
            float p00, p01, p10, p11, q00, q01, q10, q11;
            {
                int t0 = b * 2, t1 = b * 2 + 1;
                p00 = __expf(sc[t0][0] - mn0); p01 = __expf(sc[t0][1] - mn0);
                p10 = __expf(sc[t0][2] - mn1); p11 = __expf(sc[t0][3] - mn1);
                q00 = __expf(sc[t1][0] - mn0); q01 = __expf(sc[t1][1] - mn0);
                q10 = __expf(sc[t1][2] - mn1); q11 = __expf(sc[t1][3] - mn1);
            }
            ps0 += p00 + p01 + q00 + q01;
            ps1 += p10 + p11 + q10 + q11;
            __half h00 = __float2half_rn(p00), h01 = __float2half_rn(p01);
            __half h10 = __float2half_rn(p10), h11 = __float2half_rn(p11);
            __half g00 = __float2half_rn(q00), g01 = __float2half_rn(q01);
            __half g10 = __float2half_rn(q10), g11 = __float2half_rn(q11);
            pah[b][0] = pack_h2(h00, h01);
            pah[b][1] = pack_h2(h10, h11);
            pah[b][2] = pack_h2(g00, g01);
            pah[b][3] = pack_h2(g10, g11);
            pal[b][0] = pack_h2(__float2half_rn(p00 - __half2float(h00)),
                                __float2half_rn(p01 - __half2float(h01)));
            pal[b][1] = pack_h2(__float2half_rn(p10 - __half2float(h10)),
                                __float2half_rn(p11 - __half2float(h11)));
            pal[b][2] = pack_h2(__float2half_rn(q00 - __half2float(g00)),
                                __float2half_rn(q01 - __half2float(g01)));
            pal[b][3] = pack_h2(__float2half_rn(q10 - __half2float(g10)),
                                __float2half_rn(q11 - __half2float(g11)));
        }
        ps0 += __shfl_xor_sync(0xffffffffu, ps0, 1);
        ps0 += __shfl_xor_sync(0xffffffffu, ps0, 2);
        ps1 += __shfl_xor_sync(0xffffffffu, ps1, 1);
        ps1 += __shfl_xor_sync(0xffffffffu, ps1, 2);
        lrow0 = lrow0 * c0 + ps0;
        lrow1 = lrow1 * c1 + ps1;
#pragma unroll
        for (int nt = 0; nt < 16; nt++) {
            oacc[nt][0] *= c0; oacc[nt][1] *= c0;
            oacc[nt][2] *= c1; oacc[nt][3] *= c1;
        }
        uint32_t vbase = smb + (uint32_t)((64 + st * 32) * PKV) * 2;
        int loc = lane & 7, li = lane >> 3;
#pragma unroll
        for (int dp = 0; dp < 8; dp++) {
            uint32_t vf0[4], vf1[4];
            uint32_t col = dp * 16 + (li >> 1) * 8;
            ldsm_x4t(vf0, vbase + (uint32_t)(((li & 1) * 8 + loc) * PKV + col) * 2);
            ldsm_x4t(vf1, vbase + (uint32_t)((16 + (li & 1) * 8 + loc) * PKV + col) * 2);
            mma_fp16(oacc[dp * 2],     pah[0], vf0[0], vf0[1]);
            mma_fp16(oacc[dp * 2 + 1], pah[0], vf0[2], vf0[3]);
            mma_fp16(oacc[dp * 2],     pah[1], vf1[0], vf1[1]);
            mma_fp16(oacc[dp * 2 + 1], pah[1], vf1[2], vf1[3]);
            mma_fp16(oacc[dp * 2],     pal[0], vf0[0], vf0[1]);
            mma_fp16(oacc[dp * 2 + 1], pal[0], vf0[2], vf0[3]);
            mma_fp16(oacc[dp * 2],     pal[1], vf1[0], vf1[1]);
            mma_fp16(oacc[dp * 2 + 1], pal[1], vf1[2], vf1[3]);
        }
        __syncthreads();
    }

    float inv0 = 1.0f / lrow0, inv1 = 1.0f / lrow1;
    int r = q0 + wq0 + (lane >> 2);
    int cbase = h * D + (lane & 3) * 2;
#pragma unroll
    for (int nt = 0; nt < 16; nt++) {
        int c = cbase + nt * 8;
        float a0 = oacc[nt][0] * inv0, a1 = oacc[nt][1] * inv0;
        float a2 = oacc[nt][2] * inv1, a3 = oacc[nt][3] * inv1;
        *(uint32_t*)(o16 + (size_t)r * QDIM + c) =
            pack_h2(__float2half_rn(a0), __float2half_rn(a1));
        *(uint32_t*)(o16 + (size_t)(r + 8) * QDIM + c) =
            pack_h2(__float2half_rn(a2), __float2half_rn(a3));
    }
}

// ---------------- host launch ----------------
extern "C" void kernel_launch(void* const* d_in, const int* in_sizes, int n_in,
                              void* d_out, int out_size) {
    const float* hs   = (const float*)d_in[0];
    const float* cosp = (const float*)d_in[1];
    const float* sinp = (const float*)d_in[2];
    const float* Wq = (const float*)d_in[4];
    const float* bq = (const float*)d_in[5];
    const float* Wk = (const float*)d_in[6];
    const float* bk = (const float*)d_in[7];
    const float* Wv = (const float*)d_in[8];
    const float* bv = (const float*)d_in[9];
    const float* Wo = (const float*)d_in[10];
    const float* Wg = (const float*)d_in[11];
    const float* Wu = (const float*)d_in[12];
    const float* Wd = (const float*)d_in[13];
    const float* ln1 = (const float*)d_in[14];
    const float* ln2 = (const float*)d_in[15];
    const float* fln = (const float*)d_in[16];

    float *p_x, *p_qkv;
    __half *p_a16, *p_b16, *p_qh, *p_ql, *p_k16, *p_v16;
    cudaGetSymbolAddress((void**)&p_x, g_x);
    cudaGetSymbolAddress((void**)&p_qkv, g_qkv);
    cudaGetSymbolAddress((void**)&p_a16, g_a16);
    cudaGetSymbolAddress((void**)&p_b16, g_b16);
    cudaGetSymbolAddress((void**)&p_qh, g_q16h);
    cudaGetSymbolAddress((void**)&p_ql, g_q16l);
    cudaGetSymbolAddress((void**)&p_k16, g_k16);
    cudaGetSymbolAddress((void**)&p_v16, g_v16);

    const int SMEM2 = 3 * (A_BYTES + 2 * B_BYTES);  // 82944
    const int SMEM1 = 3 * (A_BYTES + B_BYTES);      // 56832
    cudaFuncSetAttribute(attn_kernel, cudaFuncAttributeMaxDynamicSharedMemorySize, ATT_SMEM);
    cudaFuncSetAttribute((wgemm_kernel<0,2>), cudaFuncAttributeMaxDynamicSharedMemorySize, SMEM2);
    cudaFuncSetAttribute((wgemm_kernel<1,2>), cudaFuncAttributeMaxDynamicSharedMemorySize, SMEM2);
    cudaFuncSetAttribute((wgemm_kernel<1,1>), cudaFuncAttributeMaxDynamicSharedMemorySize, SMEM1);
    cudaFuncSetAttribute((wgemm_kernel<2,1>), cudaFuncAttributeMaxDynamicSharedMemorySize, SMEM1);

    {
        int n4 = S * H / 4;
        copy_kernel<<<(n4 + 255) / 256, 256>>>((const float4*)hs, (float4*)p_x, n4);
    }

    for (int i = 0; i < LAYERS; i++) {
        const float* Wq_i = Wq + (size_t)i * H * QDIM;
        const float* Wk_i = Wk + (size_t)i * H * KVDIM;
        const float* Wv_i = Wv + (size_t)i * H * KVDIM;
        const float* Wo_i = Wo + (size_t)i * QDIM * H;
        const float* Wg_i = Wg + (size_t)i * H * IFF;
        const float* Wu_i = Wu + (size_t)i * H * IFF;
        const float* Wd_i = Wd + (size_t)i * IFF * H;
        const float* bq_i = bq + (size_t)i * QDIM;
        const float* bk_i = bk + (size_t)i * KVDIM;
        const float* bv_i = bv + (size_t)i * KVDIM;

        rmsnorm16_kernel<<<S, 256>>>(p_x, ln1 + (size_t)i * H, p_a16);

        // QKV: fused conversion, 2-pass
        wgemm_kernel<0,2><<<dim3(S / 128, QKVN / 128), 256, SMEM2>>>(
            p_a16, Wq_i, Wk_i, Wv_i, bq_i, bk_i, bv_i, nullptr, p_qkv, nullptr,
            H, QKVN, 0);

        rope16_kernel<<<dim3(S, NQ + 2 * NKV), 128>>>(p_qkv, cosp, sinp, p_qh, p_ql, p_k16, p_v16);
        attn_kernel<<<dim3(S / 128, NQ), 256, ATT_SMEM>>>(p_qh, p_ql, p_k16, p_v16, p_a16);

        // O-proj: fused conversion, 2-pass
        wgemm_kernel<1,2><<<dim3(S / 128, H / 128), 256, SMEM2>>>(
            p_a16, Wo_i, nullptr, nullptr, nullptr, nullptr, nullptr, p_x, p_x, nullptr,
            QDIM, H, 0);

        rmsnorm16_kernel<<<S, 256>>>(p_x, ln2 + (size_t)i * H, p_a16);

        // gate/up: fused conversion + interleave, 1-pass
        wgemm_kernel<2,1><<<dim3(S / 128, GUN / 128), 256, SMEM1>>>(
            p_a16, Wg_i, Wu_i, nullptr, nullptr, nullptr, nullptr, nullptr, nullptr, p_b16,
            H, GUN, IFF);

        // down-proj: fused conversion, 1-pass
        wgemm_kernel<1,1><<<dim3(S / 128, H / 128), 256, SMEM1>>>(
            p_b16, Wd_i, nullptr, nullptr, nullptr, nullptr, nullptr, p_x, p_x, nullptr,
            IFF, H, 0);
    }

    rmsnorm_kernel<<<S, 256>>>(p_x, fln, (float*)d_out);
}

// round 16
// speedup vs baseline: 1.3316x; 1.3316x over previous
#include <cuda_runtime.h>
#include <cuda_fp16.h>
#include <math.h>
#include <stdint.h>

#define S 2048
#define H 1536
#define NQ 12
#define NKV 2
#define D 128
#define IFF 8960
#define LAYERS 4
#define QDIM (NQ*D)      // 1536
#define KVDIM (NKV*D)    // 256
#define QKVN 2048
#define GUN (2*IFF)      // 17920
#define EPS 1e-6f
#define SCALE 0.08838834764831845f

// ---------------- device scratch (allocation-free) ----------------
__device__ float g_x[S*H];
__device__ float g_qkv[S*QKVN];
__device__ __half g_w16h[(size_t)H*GUN];
__device__ __half g_a16[(size_t)S*H];
__device__ __half g_b16[(size_t)S*IFF];
__device__ __half g_q16h[(size_t)NQ*S*D];
__device__ __half g_q16l[(size_t)NQ*S*D];
__device__ __half g_k16[(size_t)NKV*S*D];
__device__ __half g_v16[(size_t)NKV*S*D];

__device__ __forceinline__ uint32_t pack_h2(__half a, __half b) {
    __half2 t; t.x = a; t.y = b;
    return *reinterpret_cast<uint32_t*>(&t);
}
__device__ __forceinline__ uint32_t smem_u32(const void* p) {
    uint32_t a;
    asm("{ .reg .u64 t; cvta.to.shared.u64 t, %1; cvt.u32.u64 %0, t; }" : "=r"(a) : "l"(p));
    return a;
}
__device__ __forceinline__ void mma_fp16(float* d, const uint32_t* a, uint32_t b0, uint32_t b1) {
    asm volatile(
        "mma.sync.aligned.m16n8k16.row.col.f32.f16.f16.f32 "
        "{%0,%1,%2,%3}, {%4,%5,%6,%7}, {%8,%9}, {%0,%1,%2,%3};"
        : "+f"(d[0]), "+f"(d[1]), "+f"(d[2]), "+f"(d[3])
        : "r"(a[0]), "r"(a[1]), "r"(a[2]), "r"(a[3]), "r"(b0), "r"(b1));
}
__device__ __forceinline__ void ldsm_x4(uint32_t* r, uint32_t addr) {
    asm volatile("ldmatrix.sync.aligned.m8n8.x4.shared.b16 {%0,%1,%2,%3}, [%4];"
        : "=r"(r[0]), "=r"(r[1]), "=r"(r[2]), "=r"(r[3]) : "r"(addr));
}
__device__ __forceinline__ void ldsm_x4t(uint32_t* r, uint32_t addr) {
    asm volatile("ldmatrix.sync.aligned.m8n8.x4.trans.shared.b16 {%0,%1,%2,%3}, [%4];"
        : "=r"(r[0]), "=r"(r[1]), "=r"(r[2]), "=r"(r[3]) : "r"(addr));
}
#define CP_A16(dst, src) asm volatile("cp.async.ca.shared.global [%0], [%1], 16;" :: "r"(dst), "l"(src) : "memory")
#define CP_COMMIT()      asm volatile("cp.async.commit_group;" ::: "memory")
#define CP_WAIT(n)       asm volatile("cp.async.wait_group %0;" :: "n"(n) : "memory")

// ---------------- copy ----------------
__global__ void copy_kernel(const float4* __restrict__ src, float4* __restrict__ dst, int n) {
    int i = blockIdx.x * blockDim.x + threadIdx.x;
    if (i < n) dst[i] = src[i];
}

// ---------------- RMSNorm (fp32 out, final only) ----------------
__global__ void rmsnorm_kernel(const float* __restrict__ x, const float* __restrict__ w,
                               float* __restrict__ out) {
    int row = blockIdx.x;
    const float* xr = x + (size_t)row * H;
    float ss = 0.f;
    for (int c = threadIdx.x; c < H; c += 256) { float v = xr[c]; ss += v * v; }
    __shared__ float red[256];
    red[threadIdx.x] = ss;
    __syncthreads();
    for (int off = 128; off > 0; off >>= 1) {
        if (threadIdx.x < off) red[threadIdx.x] += red[threadIdx.x + off];
        __syncthreads();
    }
    float rs = 1.0f / sqrtf(red[0] / (float)H + EPS);
    float* orow = out + (size_t)row * H;
    for (int c = threadIdx.x; c < H; c += 256) orow[c] = xr[c] * rs * w[c];
}

// ---------------- RMSNorm -> fp16 ----------------
__global__ void rmsnorm16_kernel(const float* __restrict__ x, const float* __restrict__ w,
                                 __half* __restrict__ out) {
    int row = blockIdx.x;
    const float* xr = x + (size_t)row * H;
    float ss = 0.f;
    for (int c = threadIdx.x; c < H; c += 256) { float v = xr[c]; ss += v * v; }
    __shared__ float red[256];
    red[threadIdx.x] = ss;
    __syncthreads();
    for (int off = 128; off > 0; off >>= 1) {
        if (threadIdx.x < off) red[threadIdx.x] += red[threadIdx.x + off];
        __syncthreads();
    }
    float rs = 1.0f / sqrtf(red[0] / (float)H + EPS);
    for (int c = threadIdx.x * 2; c < H; c += 512) {
        float v0 = xr[c] * rs * w[c];
        float v1 = xr[c + 1] * rs * w[c + 1];
        *(uint32_t*)(out + (size_t)row * H + c) =
            pack_h2(__float2half_rn(v0), __float2half_rn(v1));
    }
}

// ---------------- fp32 -> fp16 convert helper ----------------
__device__ __forceinline__ uint4 cvt8h(const float* src) {
    float4 a = *(const float4*)src;
    float4 b = *(const float4*)(src + 4);
    uint4 r;
    r.x = pack_h2(__float2half_rn(a.x), __float2half_rn(a.y));
    r.y = pack_h2(__float2half_rn(a.z), __float2half_rn(a.w));
    r.z = pack_h2(__float2half_rn(b.x), __float2half_rn(b.y));
    r.w = pack_h2(__float2half_rn(b.z), __float2half_rn(b.w));
    return r;
}

// ---------------- weight convert (streaming, hi only, optional column placement) ----------------
__global__ void wcvt_kernel(const float* __restrict__ W, int total8, int nc8,
                            __half* __restrict__ Th, int coff, int ldn) {
    int i = blockIdx.x * 256 + threadIdx.x;
    if (i >= total8) return;
    int k = i / nc8;
    int n = (i - k * nc8) * 8;
    uint4 hv = cvt8h(W + (size_t)k * (nc8 * 8) + n);
    *(uint4*)(Th + (size_t)k * ldn + coff + n) = hv;
}

// gate/up interleave at 32 cols: dst col = (n/32)*64 + n%32 + up*32
__global__ void wcvt_gu_kernel(const float* __restrict__ W, int up,
                               __half* __restrict__ Th) {
    int i = blockIdx.x * 256 + threadIdx.x;
    if (i >= H * IFF / 8) return;
    int k = i / (IFF / 8);
    int n = (i - k * (IFF / 8)) * 8;
    uint4 hv = cvt8h(W + (size_t)k * IFF + n);
    int c = ((n >> 5) << 6) + (n & 31) + up * 32;
    *(uint4*)(Th + (size_t)k * GUN + c) = hv;
}

// ---------------- warp-MMA fp16 1-pass GEMM, TM=128, 3-stage, occ 2 ----------------
// EPI 0: += qkv bias -> fp32; 1: += R -> fp32; 2: silu(g)*u -> fp16.
#define APITCH 40
#define PB 136
#define B_BYTES (32 * PB * 2)            // 8704
#define A_BYTES (128 * APITCH * 2)       // 10240
#define STAGE_BYTES (A_BYTES + B_BYTES)  // 18944
#define GEMM_SMEM (3 * STAGE_BYTES)      // 56832

template <int EPI>
__global__ void __launch_bounds__(256, 2) wgemm_kernel(
    const __half* __restrict__ A,
    const __half* __restrict__ Bh, int ldb,
    const float* __restrict__ bq, const float* __restrict__ bk, const float* __restrict__ bv,
    const float* __restrict__ Rres, float* __restrict__ C,
    __half* __restrict__ C16,
    int K, int N, int Nout)
{
    extern __shared__ char smc[];
    uint32_t smb = smem_u32(smc);
    int tid = threadIdx.x, wid = tid >> 5, lane = tid & 31;
    int bm = blockIdx.x * 128, bn = blockIdx.y * 128;
    int mw = (wid & 3) * 32, nw = (wid >> 2) * 64;
    const int KS = K / 32;

    int arow = tid >> 1, akoff = (tid & 1) * 16;
    const __half* Ap = A + (size_t)(bm + arow) * K + akoff;
    uint32_t a_s = (uint32_t)(arow * APITCH + akoff) * 2;

    int brow = tid >> 3, bcoff = (tid & 7) * 16;
    const __half* Bhp = Bh + (size_t)brow * ldb + bn + bcoff;
    uint32_t b_s = (uint32_t)(brow * PB + bcoff) * 2;

    auto cpstage = [&](int st, int k0) {
        uint32_t base = smb + (uint32_t)st * STAGE_BYTES;
        CP_A16(base + a_s,      Ap + k0);
        CP_A16(base + a_s + 16, Ap + k0 + 8);
        const __half* sbh = Bhp + (size_t)k0 * ldb;
        CP_A16(base + A_BYTES + b_s,      sbh);
        CP_A16(base + A_BYTES + b_s + 16, sbh + 8);
    };

    float acc[2][8][4];
#pragma unroll
    for (int mt = 0; mt < 2; mt++)
#pragma unroll
        for (int nt = 0; nt < 8; nt++)
#pragma unroll
            for (int e = 0; e < 4; e++) acc[mt][nt][e] = 0.f;

    const int frow = lane & 15, fk8 = (lane >> 4) << 3;
    const int loc = lane & 7, li = lane >> 3;

    cpstage(0, 0); CP_COMMIT();
    cpstage(1, 32); CP_COMMIT();

    int st = 0;
    for (int ks = 0; ks < KS; ks++) {
        CP_WAIT(1);
        __syncthreads();
        if (ks + 2 < KS) {
            int nst = st + 2; if (nst >= 3) nst -= 3;
            cpstage(nst, (ks + 2) * 32);
            CP_COMMIT();
        }
        uint32_t A32  = smb + (uint32_t)st * STAGE_BYTES;
        uint32_t Bh32 = A32 + A_BYTES;

#pragma unroll
        for (int kk = 0; kk < 32; kk += 16) {
            uint32_t ah[2][4];
#pragma unroll
            for (int mt = 0; mt < 2; mt++) {
                uint32_t off = (uint32_t)((mw + mt * 16 + frow) * APITCH + kk + fk8) * 2;
                ldsm_x4(ah[mt], A32 + off);
            }
#pragma unroll
            for (int p = 0; p < 4; p++) {
                uint32_t boff = (uint32_t)((kk + (li & 1) * 8 + loc) * PB
                                           + nw + p * 16 + (li >> 1) * 8) * 2;
                uint32_t bh[4];
                ldsm_x4t(bh, Bh32 + boff);
#pragma unroll
                for (int o = 0; o < 2; o++) {
                    int nt = p * 2 + o;
#pragma unroll
                    for (int mt = 0; mt < 2; mt++)
                        mma_fp16(acc[mt][nt], ah[mt], bh[o * 2], bh[o * 2 + 1]);
                }
            }
        }
        st++; if (st >= 3) st = 0;
    }

    // ---- epilogue ----
    if (EPI == 2) {
        int j = (bn + nw) >> 6;
#pragma unroll
        for (int mt = 0; mt < 2; mt++) {
#pragma unroll
            for (int nt = 0; nt < 4; nt++) {
                int r0 = bm + mw + mt * 16 + (lane >> 2);
                int col = (j << 5) + nt * 8 + (lane & 3) * 2;
                float av[4];
#pragma unroll
                for (int e = 0; e < 4; e++) {
                    float g = acc[mt][nt][e];
                    float u = acc[mt][nt + 4][e];
                    av[e] = g / (1.f + __expf(-g)) * u;
                }
                *(uint32_t*)(C16 + (size_t)r0 * Nout + col) =
                    pack_h2(__float2half_rn(av[0]), __float2half_rn(av[1]));
                *(uint32_t*)(C16 + (size_t)(r0 + 8) * Nout + col) =
                    pack_h2(__float2half_rn(av[2]), __float2half_rn(av[3]));
            }
        }
    } else {
#pragma unroll
        for (int mt = 0; mt < 2; mt++) {
#pragma unroll
            for (int nt = 0; nt < 8; nt++) {
                int r0 = bm + mw + mt * 16 + (lane >> 2);
                int col = bn + nw + nt * 8 + (lane & 3) * 2;
                float2 v0 = {acc[mt][nt][0], acc[mt][nt][1]};
                float2 v1 = {acc[mt][nt][2], acc[mt][nt][3]};
                if (EPI == 0) {
                    float b0, b1;
                    if (col < QDIM)              { b0 = bq[col];                b1 = bq[col + 1]; }
                    else if (col < QDIM + KVDIM) { b0 = bk[col - QDIM];         b1 = bk[col - QDIM + 1]; }
                    else                         { b0 = bv[col - QDIM - KVDIM]; b1 = bv[col - QDIM - KVDIM + 1]; }
                    v0.x += b0; v0.y += b1; v1.x += b0; v1.y += b1;
                } else {
                    float2 r0v = *(const float2*)(Rres + (size_t)r0 * N + col);
                    float2 r1v = *(const float2*)(Rres + (size_t)(r0 + 8) * N + col);
                    v0.x += r0v.x; v0.y += r0v.y;
                    v1.x += r1v.x; v1.y += r1v.y;
                }
                *(float2*)(C + (size_t)r0 * N + col) = v0;
                *(float2*)(C + (size_t)(r0 + 8) * N + col) = v1;
            }
        }
    }
}

// ---------------- RoPE -> fp16 Q split + fp16 K/V ----------------
__global__ void rope16_kernel(const float* __restrict__ qkv,
                              const float* __restrict__ cp, const float* __restrict__ sp,
                              __half* __restrict__ qh, __half* __restrict__ ql,
                              __half* __restrict__ k16, __half* __restrict__ v16) {
    int s = blockIdx.x, slot = blockIdx.y, d = threadIdx.x;
    float c = cp[s * D + d], sn = sp[s * D + d];
    const float* row;
    if (slot < NQ)            row = qkv + (size_t)s * QKVN + slot * D;
    else if (slot < NQ + NKV) row = qkv + (size_t)s * QKVN + QDIM + (slot - NQ) * D;
    else                      row = qkv + (size_t)s * QKVN + QDIM + KVDIM + (slot - NQ - NKV) * D;
    float a = row[d];
    float b = row[d ^ 64];
    float rot = (d < 64) ? -b : b;
    if (slot < NQ) {
        float val = a * c + rot * sn;
        __half hv = __float2half_rn(val);
        __half lv = __float2half_rn(val - __half2float(hv));
        size_t o = ((size_t)slot * S + s) * D + d;
        qh[o] = hv; ql[o] = lv;
    } else if (slot < NQ + NKV) {
        float val = a * c + rot * sn;
        k16[((size_t)(slot - NQ) * S + s) * D + d] = __float2half_rn(val);
    } else {
        v16[((size_t)(slot - NQ - NKV) * S + s) * D + d] = __float2half_rn(a);
    }
}

// ---------------- tensor-core causal flash attention ----------------
#define PKV 136
#define ATT_SMEM (128 * PKV * 2)

__global__ void __launch_bounds__(256, 1) attn_kernel(
    const __half* __restrict__ qh, const __half* __restrict__ ql,
    const __half* __restrict__ k16, const __half* __restrict__ v16,
    __half* __restrict__ o16)
{
    extern __shared__ __half sma[];
    uint32_t smb = smem_u32(sma);
    int tid = threadIdx.x, wid = tid >> 5, lane = tid & 31;
    int bq = (int)gridDim.x - 1 - (int)blockIdx.x;
    int h = blockIdx.y;
    int kvh = h / (NQ / NKV);
    int q0 = bq * 128;
    int wq0 = wid * 16;

    const int frow = lane & 15, fk8 = (lane >> 4) << 3;

    uint32_t qfh[8][4], qfl[8][4];
    {
        int row = tid >> 1, coff = (tid & 1) * 64;
        __half* dst = sma + row * PKV + coff;
        const __half* src = qh + ((size_t)h * S + q0 + row) * D + coff;
#pragma unroll
        for (int j = 0; j < 8; j++) *(uint4*)(dst + j * 8) = *(const uint4*)(src + j * 8);
        __syncthreads();
#pragma unroll
        for (int kd = 0; kd < 8; kd++)
            ldsm_x4(qfh[kd], smb + (uint32_t)((wq0 + frow) * PKV + kd * 16 + fk8) * 2);
        __syncthreads();
        const __half* src2 = ql + ((size_t)h * S + q0 + row) * D + coff;
#pragma unroll
        for (int j = 0; j < 8; j++) *(uint4*)(dst + j * 8) = *(const uint4*)(src2 + j * 8);
        __syncthreads();
#pragma unroll
        for (int kd = 0; kd < 8; kd++)
            ldsm_x4(qfl[kd], smb + (uint32_t)((wq0 + frow) * PKV + kd * 16 + fk8) * 2);
        __syncthreads();
    }

    auto cp_kv = [&](int st, int kt) {
        int row = tid >> 3, c16 = (tid & 7) * 16;
        const __half* ksrc = k16 + ((size_t)kvh * S + kt * 32 + row) * D + c16;
        const __half* vsrc = v16 + ((size_t)kvh * S + kt * 32 + row) * D + c16;
        uint32_t kdst = smb + (uint32_t)((st * 32 + row) * PKV + c16) * 2;
        uint32_t vdst = smb + (uint32_t)((64 + st * 32 + row) * PKV + c16) * 2;
        CP_A16(kdst, ksrc); CP_A16(kdst + 16, ksrc + 8);
        CP_A16(vdst, vsrc); CP_A16(vdst + 16, vsrc + 8);
    };

    float oacc[16][4];
#pragma unroll
    for (int nt = 0; nt < 16; nt++)
#pragma unroll
        for (int e = 0; e < 4; e++) oacc[nt][e] = 0.f;
    float mrow0 = -1e30f, mrow1 = -1e30f, lrow0 = 0.f, lrow1 = 0.f;

    const int nk = 4 * bq + 4;
    cp_kv(0, 0);
    CP_COMMIT();

    for (int kt = 0; kt < nk; kt++) {
        int st = kt & 1;
        if (kt + 1 < nk) {
            cp_kv(st ^ 1, kt + 1);
            CP_COMMIT();
            CP_WAIT(1);
        } else {
            CP_WAIT(0);
        }
        __syncthreads();

        float sc[4][4];
#pragma unroll
        for (int nt = 0; nt < 4; nt++)
#pragma unroll
            for (int e = 0; e < 4; e++) sc[nt][e] = 0.f;
        uint32_t kbase = smb + (uint32_t)(st * 32 * PKV) * 2;
#pragma unroll
        for (int kd = 0; kd < 8; kd++) {
            uint32_t bf0[4], bf1[4];
            ldsm_x4(bf0, kbase + (uint32_t)(frow * PKV + kd * 16 + fk8) * 2);
            ldsm_x4(bf1, kbase + (uint32_t)((16 + frow) * PKV + kd * 16 + fk8) * 2);
            mma_fp16(sc[0], qfh[kd], bf0[0], bf0[2]);
            mma_fp16(sc[1], qfh[kd], bf0[1], bf0[3]);
            mma_fp16(sc[2], qfh[kd], bf1[0], bf1[2]);
            mma_fp16(sc[3], qfh[kd], bf1[1], bf1[3]);
            mma_fp16(sc[0], qfl[kd], bf0[0], bf0[2]);
            mma_fp16(sc[1], qfl[kd], bf0[1], bf0[3]);
            mma_fp16(sc[2], qfl[kd], bf1[0], bf1[2]);
            mma_fp16(sc[3], qfl[kd], bf1[1], bf1[3]);
        }
        int r_lo = q0 + wq0 + (lane >> 2);
        if (kt >= 4 * bq) {
            int kk0 = kt * 32;
#pragma unroll
            for (int nt = 0; nt < 4; nt++) {
                int kc = kk0 + nt * 8 + (lane & 3) * 2;
#pragma unroll
                for (int e = 0; e < 4; e++) {
                    int key = kc + (e & 1);
                    int row = r_lo + ((e >> 1) << 3);
                    sc[nt][e] = (key > row) ? -1e30f : sc[nt][e] * SCALE;
                }
            }
        } else {
#pragma unroll
            for (int nt = 0; nt < 4; nt++)
#pragma unroll
                for (int e = 0; e < 4; e++) sc[nt][e] *= SCALE;
        }
        float mx0 = -1e30f, mx1 = -1e30f;
#pragma unroll
        for (int nt = 0; nt < 4; nt++) {
            mx0 = fmaxf(mx0, fmaxf(sc[nt][0], sc[nt][1]));
            mx1 = fmaxf(mx1, fmaxf(sc[nt][2], sc[nt][3]));
        }
        mx0 = fmaxf(mx0, __shfl_xor_sync(0xffffffffu, mx0, 1));
        mx0 = fmaxf(mx0, __shfl_xor_sync(0xffffffffu, mx0, 2));
        mx1 = fmaxf(mx1, __shfl_xor_sync(0xffffffffu, mx1, 1));
        mx1 = fmaxf(mx1, __shfl_xor_sync(0xffffffffu, mx1, 2));
        float mn0 = fmaxf(mrow0, mx0), mn1 = fmaxf(mrow1, mx1);
        float c0 = __expf(mrow0 - mn0), c1 = __expf(mrow1 - mn1);
        mrow0 = mn0; mrow1 = mn1;
        uint32_t pah[2][4], pal[2][4];
        float ps0 = 0.f, ps1 = 0.f;
#pragma unroll
        for (int b = 0; b < 2; b++) {
            float p00, p01, p10, p11, q00, q01, q10, q11;
            {
                int t0 = b * 2, t1 = b * 2 + 1;
                p00 = __expf(sc[t0][0] - mn0); p01 = __expf(sc[t0][1] - mn0);
                p10 = __expf(sc[t0][2] - mn1); p11 = __expf(sc[t0][3] - mn1);
                q00 = __expf(sc[t1][0] - mn0); q01 = __expf(sc[t1][1] - mn0);
                q10 = __expf(sc[t1][2] - mn1); q11 = __expf(sc[t1][3] - mn1);
            }
            ps0 += p00 + p01 + q00 + q01;
            ps1 += p10 + p11 + q10 + q11;
            __half h00 = __float2half_rn(p00), h01 = __float2half_rn(p01);
            __half h10 = __float2half_rn(p10), h11 = __float2half_rn(p11);
            __half g00 = __float2half_rn(q00), g01 = __float2half_rn(q01);
            __half g10 = __float2half_rn(q10), g11 = __float2half_rn(q11);
            pah[b][0] = pack_h2(h00, h01);
            pah[b][1] = pack_h2(h10, h11);
            pah[b][2] = pack_h2(g00, g01);
            pah[b][3] = pack_h2(g10, g11);
            pal[b][0] = pack_h2(__float2half_rn(p00 - __half2float(h00)),
                                __float2half_rn(p01 - __half2float(h01)));
            pal[b][1] = pack_h2(__float2half_rn(p10 - __half2float(h10)),
                                __float2half_rn(p11 - __half2float(h11)));
            pal[b][2] = pack_h2(__float2half_rn(q00 - __half2float(g00)),
                                __float2half_rn(q01 - __half2float(g01)));
            pal[b][3] = pack_h2(__float2half_rn(q10 - __half2float(g10)),
                                __float2half_rn(q11 - __half2float(g11)));
        }
        ps0 += __shfl_xor_sync(0xffffffffu, ps0, 1);
        ps0 += __shfl_xor_sync(0xffffffffu, ps0, 2);
        ps1 += __shfl_xor_sync(0xffffffffu, ps1, 1);
        ps1 += __shfl_xor_sync(0xffffffffu, ps1, 2);
        lrow0 = lrow0 * c0 + ps0;
        lrow1 = lrow1 * c1 + ps1;
#pragma unroll
        for (int nt = 0; nt < 16; nt++) {
            oacc[nt][0] *= c0; oacc[nt][1] *= c0;
            oacc[nt][2] *= c1; oacc[nt][3] *= c1;
        }
        uint32_t vbase = smb + (uint32_t)((64 + st * 32) * PKV) * 2;
        int loc = lane & 7, li = lane >> 3;
#pragma unroll
        for (int dp = 0; dp < 8; dp++) {
            uint32_t vf0[4], vf1[4];
            uint32_t col = dp * 16 + (li >> 1) * 8;
            ldsm_x4t(vf0, vbase + (uint32_t)(((li & 1) * 8 + loc) * PKV + col) * 2);
            ldsm_x4t(vf1, vbase + (uint32_t)((16 + (li & 1) * 8 + loc) * PKV + col) * 2);
            mma_fp16(oacc[dp * 2],     pah[0], vf0[0], vf0[1]);
            mma_fp16(oacc[dp * 2 + 1], pah[0], vf0[2], vf0[3]);
            mma_fp16(oacc[dp * 2],     pah[1], vf1[0], vf1[1]);
            mma_fp16(oacc[dp * 2 + 1], pah[1], vf1[2], vf1[3]);
            mma_fp16(oacc[dp * 2],     pal[0], vf0[0], vf0[1]);
            mma_fp16(oacc[dp * 2 + 1], pal[0], vf0[2], vf0[3]);
            mma_fp16(oacc[dp * 2],     pal[1], vf1[0], vf1[1]);
            mma_fp16(oacc[dp * 2 + 1], pal[1], vf1[2], vf1[3]);
        }
        __syncthreads();
    }

    float inv0 = 1.0f / lrow0, inv1 = 1.0f / lrow1;
    int r = q0 + wq0 + (lane >> 2);
    int cbase = h * D + (lane & 3) * 2;
#pragma unroll
    for (int nt = 0; nt < 16; nt++) {
        int c = cbase + nt * 8;
        float a0 = oacc[nt][0] * inv0, a1 = oacc[nt][1] * inv0;
        float a2 = oacc[nt][2] * inv1, a3 = oacc[nt][3] * inv1;
        *(uint32_t*)(o16 + (size_t)r * QDIM + c) =
            pack_h2(__float2half_rn(a0), __float2half_rn(a1));
        *(uint32_t*)(o16 + (size_t)(r + 8) * QDIM + c) =
            pack_h2(__float2half_rn(a2), __float2half_rn(a3));
    }
}

// ---------------- host launch ----------------
extern "C" void kernel_launch(void* const* d_in, const int* in_sizes, int n_in,
                              void* d_out, int out_size) {
    const float* hs   = (const float*)d_in[0];
    const float* cosp = (const float*)d_in[1];
    const float* sinp = (const float*)d_in[2];
    const float* Wq = (const float*)d_in[4];
    const float* bq = (const float*)d_in[5];
    const float* Wk = (const float*)d_in[6];
    const float* bk = (const float*)d_in[7];
    const float* Wv = (const float*)d_in[8];
    const float* bv = (const float*)d_in[9];
    const float* Wo = (const float*)d_in[10];
    const float* Wg = (const float*)d_in[11];
    const float* Wu = (const float*)d_in[12];
    const float* Wd = (const float*)d_in[13];
    const float* ln1 = (const float*)d_in[14];
    const float* ln2 = (const float*)d_in[15];
    const float* fln = (const float*)d_in[16];

    float *p_x, *p_qkv;
    __half *p_wh, *p_a16, *p_b16, *p_qh, *p_ql, *p_k16, *p_v16;
    cudaGetSymbolAddress((void**)&p_x, g_x);
    cudaGetSymbolAddress((void**)&p_qkv, g_qkv);
    cudaGetSymbolAddress((void**)&p_wh, g_w16h);
    cudaGetSymbolAddress((void**)&p_a16, g_a16);
    cudaGetSymbolAddress((void**)&p_b16, g_b16);
    cudaGetSymbolAddress((void**)&p_qh, g_q16h);
    cudaGetSymbolAddress((void**)&p_ql, g_q16l);
    cudaGetSymbolAddress((void**)&p_k16, g_k16);
    cudaGetSymbolAddress((void**)&p_v16, g_v16);

    cudaFuncSetAttribute(attn_kernel, cudaFuncAttributeMaxDynamicSharedMemorySize, ATT_SMEM);
    cudaFuncSetAttribute(wgemm_kernel<0>, cudaFuncAttributeMaxDynamicSharedMemorySize, GEMM_SMEM);
    cudaFuncSetAttribute(wgemm_kernel<1>, cudaFuncAttributeMaxDynamicSharedMemorySize, GEMM_SMEM);
    cudaFuncSetAttribute(wgemm_kernel<2>, cudaFuncAttributeMaxDynamicSharedMemorySize, GEMM_SMEM);

    {
        int n4 = S * H / 4;
        copy_kernel<<<(n4 + 255) / 256, 256>>>((const float4*)hs, (float4*)p_x, n4);
    }

    for (int i = 0; i < LAYERS; i++) {
        const float* Wq_i = Wq + (size_t)i * H * QDIM;
        const float* Wk_i = Wk + (size_t)i * H * KVDIM;
        const float* Wv_i = Wv + (size_t)i * H * KVDIM;
        const float* Wo_i = Wo + (size_t)i * QDIM * H;
        const float* Wg_i = Wg + (size_t)i * H * IFF;
        const float* Wu_i = Wu + (size_t)i * H * IFF;
        const float* Wd_i = Wd + (size_t)i * IFF * H;
        const float* bq_i = bq + (size_t)i * QDIM;
        const float* bk_i = bk + (size_t)i * KVDIM;
        const float* bv_i = bv + (size_t)i * KVDIM;

        rmsnorm16_kernel<<<S, 256>>>(p_x, ln1 + (size_t)i * H, p_a16);

        // QKV: 1-pass fp16, concat layout
        wcvt_kernel<<<(H * QDIM / 8 + 255) / 256, 256>>>(
            Wq_i, H * QDIM / 8, QDIM / 8, p_wh, 0, QKVN);
        wcvt_kernel<<<(H * KVDIM / 8 + 255) / 256, 256>>>(
            Wk_i, H * KVDIM / 8, KVDIM / 8, p_wh, QDIM, QKVN);
        wcvt_kernel<<<(H * KVDIM / 8 + 255) / 256, 256>>>(
            Wv_i, H * KVDIM / 8, KVDIM / 8, p_wh, QDIM + KVDIM, QKVN);
        wgemm_kernel<0><<<dim3(S / 128, QKVN / 128), 256, GEMM_SMEM>>>(
            p_a16, p_wh, QKVN, bq_i, bk_i, bv_i, nullptr, p_qkv, nullptr,
            H, QKVN, 0);

        rope16_kernel<<<dim3(S, NQ + 2 * NKV), 128>>>(p_qkv, cosp, sinp, p_qh, p_ql, p_k16, p_v16);
        attn_kernel<<<dim3(S / 128, NQ), 256, ATT_SMEM>>>(p_qh, p_ql, p_k16, p_v16, p_a16);

        // O-proj: 1-pass fp16
        wcvt_kernel<<<(QDIM * H / 8 + 255) / 256, 256>>>(
            Wo_i, QDIM * H / 8, H / 8, p_wh, 0, H);
        wgemm_kernel<1><<<dim3(S / 128, H / 128), 256, GEMM_SMEM>>>(
            p_a16, p_wh, H, nullptr, nullptr, nullptr, p_x, p_x, nullptr,
            QDIM, H, 0);

        rmsnorm16_kernel<<<S, 256>>>(p_x, ln2 + (size_t)i * H, p_a16);

        // gate/up: 1-pass fp16, interleaved
        wcvt_gu_kernel<<<(H * IFF / 8 + 255) / 256, 256>>>(Wg_i, 0, p_wh);
        wcvt_gu_kernel<<<(H * IFF / 8 + 255) / 256, 256>>>(Wu_i, 1, p_wh);
        wgemm_kernel<2><<<dim3(S / 128, GUN / 128), 256, GEMM_SMEM>>>(
            p_a16, p_wh, GUN, nullptr, nullptr, nullptr, nullptr, nullptr, p_b16,
            H, GUN, IFF);

        // down-proj: 1-pass fp16
        wcvt_kernel<<<(IFF * H / 8 + 255) / 256, 256>>>(
            Wd_i, IFF * H / 8, H / 8, p_wh, 0, H);
        wgemm_kernel<1><<<dim3(S / 128, H / 128), 256, GEMM_SMEM>>>(
            p_b16, p_wh, H, nullptr, nullptr, nullptr, p_x, p_x, nullptr,
            IFF, H, 0);
    }

    rmsnorm_kernel<<<S, 256>>>(p_x, fln, (float*)d_out);
}